// round 9
// baseline (speedup 1.0000x reference)
#include <cuda_runtime.h>
#include <cuda_fp16.h>
#include <stdint.h>

// ---------------------------------------------------------------------------
// Problem constants: B=4, S=4096, D=128, DA=64
// ---------------------------------------------------------------------------
#define B_DIM 4
#define S_DIM 4096
#define D_VAL 128
#define D_ATT 64
#define ROWS_TOTAL (B_DIM * S_DIM)   // 16384
#define W_ROWS 256                   // Wq(64) + Wk(64) + Wv(128)

// fp16 scratch (device globals: allocation-free per harness rules)
__device__ __align__(128) __half g_Qh[ROWS_TOTAL * D_ATT];
__device__ __align__(128) __half g_Kh[ROWS_TOTAL * D_ATT];
__device__ __align__(128) __half g_Vh[(size_t)ROWS_TOTAL * D_VAL];
__device__ __align__(128) __half g_Wh[W_ROWS * D_VAL];
__device__ __align__(128) __half g_Wl[W_ROWS * D_VAL];

// ---------------------------------------------------------------------------
// Small PTX helpers
// ---------------------------------------------------------------------------
#define CP_ASYNC16(dst, src) \
    asm volatile("cp.async.cg.shared.global [%0], [%1], 16;" \
                 :: "r"(dst), "l"(src) : "memory")
#define CP_COMMIT() asm volatile("cp.async.commit_group;" ::: "memory")
#define CP_WAIT(n)  asm volatile("cp.async.wait_group %0;" :: "n"(n) : "memory")

__device__ __forceinline__ uint32_t pack_f16x2(float f0, float f1) {
    // low 16 bits = f16(f0), high 16 bits = f16(f1)
    uint32_t r;
    asm("cvt.rn.f16x2.f32 %0, %1, %2;" : "=r"(r) : "f"(f1), "f"(f0));
    return r;
}

__device__ __forceinline__ uint32_t ex2_f16x2(uint32_t s) {
    uint32_t r;
    asm("ex2.approx.f16x2 %0, %1;" : "=r"(r) : "r"(s));
    return r;
}

__device__ __forceinline__ float h2f_lo(uint32_t u) {
    float f;
    asm("{ .reg .b16 h; mov.b16 h, %1; cvt.f32.f16 %0, h; }"
        : "=f"(f) : "h"((unsigned short)(u & 0xffffu)));
    return f;
}
__device__ __forceinline__ float h2f_hi(uint32_t u) {
    float f;
    asm("{ .reg .b16 h; mov.b16 h, %1; cvt.f32.f16 %0, h; }"
        : "=f"(f) : "h"((unsigned short)(u >> 16)));
    return f;
}

__device__ __forceinline__ uint32_t s2u(const void* p) {
    uint32_t a;
    asm("{ .reg .u64 t; cvta.to.shared.u64 t, %1; cvt.u32.u64 %0, t; }"
        : "=r"(a) : "l"(p));
    return a;
}

__device__ __forceinline__ void ldsm_x4(uint32_t (&r)[4], uint32_t addr) {
    asm volatile("ldmatrix.sync.aligned.m8n8.x4.shared.b16 {%0,%1,%2,%3}, [%4];"
                 : "=r"(r[0]), "=r"(r[1]), "=r"(r[2]), "=r"(r[3]) : "r"(addr));
}
__device__ __forceinline__ void ldsm_x4_t(uint32_t (&r)[4], uint32_t addr) {
    asm volatile("ldmatrix.sync.aligned.m8n8.x4.trans.shared.b16 {%0,%1,%2,%3}, [%4];"
                 : "=r"(r[0]), "=r"(r[1]), "=r"(r[2]), "=r"(r[3]) : "r"(addr));
}
__device__ __forceinline__ void stsm_x4(uint32_t addr, const uint32_t (&r)[4]) {
    asm volatile("stmatrix.sync.aligned.m8n8.x4.shared.b16 [%0], {%1,%2,%3,%4};"
                 :: "r"(addr), "r"(r[0]), "r"(r[1]), "r"(r[2]), "r"(r[3])
                 : "memory");
}

__device__ __forceinline__ void mma_f16(float (&c)[4], const uint32_t (&a)[4],
                                        uint32_t b0, uint32_t b1) {
    asm volatile(
        "mma.sync.aligned.m16n8k16.row.col.f32.f16.f16.f32 "
        "{%0,%1,%2,%3},{%4,%5,%6,%7},{%8,%9},{%0,%1,%2,%3};"
        : "+f"(c[0]), "+f"(c[1]), "+f"(c[2]), "+f"(c[3])
        : "r"(a[0]), "r"(a[1]), "r"(a[2]), "r"(a[3]), "r"(b0), "r"(b1));
}

// ---------------------------------------------------------------------------
// Kernel 0: split weights into fp16 hi/lo, concatenated [Q(64) K(64) V(128)].
// ---------------------------------------------------------------------------
__global__ void __launch_bounds__(256) wconv_kernel(
    const float* __restrict__ Wq,
    const float* __restrict__ Wk,
    const float* __restrict__ Wv)
{
    const int gid = blockIdx.x * 256 + threadIdx.x;
    if (gid >= W_ROWS * D_VAL) return;
    const int row = gid >> 7;
    const int col = gid & 127;
    float v = (row < 64)  ? Wq[row * D_VAL + col]
            : (row < 128) ? Wk[(row - 64) * D_VAL + col]
                          : Wv[(row - 128) * D_VAL + col];
    uint32_t h = pack_f16x2(v, 0.f);
    g_Wh[gid] = __ushort_as_half((unsigned short)(h & 0xffffu));
    g_Wl[gid] = __float2half_rn(v - h2f_lo(h));
}

// ---------------------------------------------------------------------------
// Kernel 1: QKV projection on tensor cores (fp16 x3-pass: AhBh + AlBh + AhBl).
// Grid: 128 CTAs x 128 x-rows. 256 threads = 8 warps.
// ---------------------------------------------------------------------------
#define PX_H 0
#define PX_L (128 * 272)                   // 34816
#define PWBUF (2 * 128 * 272)              // 69632 ; per buf: h@0, l@+17408
#define PW_BUF_SZ (2 * 64 * 272)           // 34816
#define PROJ_SMEM (PWBUF + 2 * PW_BUF_SZ)  // 139264

__global__ void __launch_bounds__(256, 1) proj_mma_kernel(
    const float* __restrict__ x)
{
    extern __shared__ char smc[];
    const uint32_t sb = s2u(smc);
    const int tid  = threadIdx.x;
    const int wid  = tid >> 5;
    const int lane = tid & 31;
    const int row0 = blockIdx.x * 128;
    const int g  = lane >> 2;
    const int t4 = lane & 3;

    #pragma unroll
    for (int i = 0; i < 4; i++) {
        int u = tid + i * 256;
        int rr = u >> 4, cc = u & 15;
        uint32_t d = sb + PWBUF + rr * 272 + cc * 16;
        CP_ASYNC16(d,         (const char*)g_Wh + (size_t)rr * 256 + cc * 16);
        CP_ASYNC16(d + 17408, (const char*)g_Wl + (size_t)rr * 256 + cc * 16);
    }
    CP_COMMIT();

    #pragma unroll
    for (int i = 0; i < 16; i++) {
        int f4 = tid + i * 256;                    // 4096 float4 = 128x128
        int row = f4 >> 5, c4 = f4 & 31;
        float4 v = *(const float4*)(x + (size_t)(row0 + row) * D_VAL + c4 * 4);
        uint32_t h01 = pack_f16x2(v.x, v.y);
        uint32_t h23 = pack_f16x2(v.z, v.w);
        uint32_t l01 = pack_f16x2(v.x - h2f_lo(h01), v.y - h2f_hi(h01));
        uint32_t l23 = pack_f16x2(v.z - h2f_lo(h23), v.w - h2f_hi(h23));
        int off = row * 272 + c4 * 8;
        *(uint2*)(smc + off + PX_H) = make_uint2(h01, h23);
        *(uint2*)(smc + off + PX_L) = make_uint2(l01, l23);
    }
    CP_WAIT(0);
    __syncthreads();

    uint32_t ah[8][4], al[8][4];
    {
        const int rowq = wid * 16 + (lane & 15);
        const int colh = (lane >> 4) * 8;
        #pragma unroll
        for (int ks = 0; ks < 8; ks++) {
            uint32_t a = sb + PX_H + rowq * 272 + (ks * 16 + colh) * 2;
            ldsm_x4(ah[ks], a);
            ldsm_x4(al[ks], a + PX_L);
        }
    }

    const int krow = lane & 7;
    const int kq   = (lane >> 3) & 3;

    #pragma unroll 1
    for (int c = 0; c < 4; c++) {
        const int buf = c & 1;

        if (c < 3) {
            #pragma unroll
            for (int i = 0; i < 4; i++) {
                int u = tid + i * 256;
                int rr = u >> 4, cc = u & 15;
                uint32_t d = sb + PWBUF + (buf ^ 1) * PW_BUF_SZ + rr * 272 + cc * 16;
                const size_t gs = (size_t)((c + 1) * 64 + rr) * 256 + cc * 16;
                CP_ASYNC16(d,         (const char*)g_Wh + gs);
                CP_ASYNC16(d + 17408, (const char*)g_Wl + gs);
            }
            CP_COMMIT();
        }

        const uint32_t wb = sb + PWBUF + buf * PW_BUF_SZ;

        float C[8][4];
        #pragma unroll
        for (int i = 0; i < 8; i++)
            #pragma unroll
            for (int j = 0; j < 4; j++) C[i][j] = 0.f;

        #pragma unroll
        for (int kp = 0; kp < 4; kp++) {
            #pragma unroll
            for (int nt = 0; nt < 8; nt++) {
                uint32_t a = wb + (nt * 8 + krow) * 272 + (kp * 32 + kq * 8) * 2;
                uint32_t bh[4], bl[4];
                ldsm_x4(bh, a);
                ldsm_x4(bl, a + 17408);
                mma_f16(C[nt], ah[2 * kp],     bh[0], bh[1]);
                mma_f16(C[nt], al[2 * kp],     bh[0], bh[1]);
                mma_f16(C[nt], ah[2 * kp],     bl[0], bl[1]);
                mma_f16(C[nt], ah[2 * kp + 1], bh[2], bh[3]);
                mma_f16(C[nt], al[2 * kp + 1], bh[2], bh[3]);
                mma_f16(C[nt], ah[2 * kp + 1], bl[2], bl[3]);
            }
        }

        const float sc = (c == 0) ? 0.18033688f : 1.0f;  // 0.125 * log2(e)
        __half* dst;
        int ldd, col0;
        if (c == 0)      { dst = g_Qh; ldd = D_ATT; col0 = 0; }
        else if (c == 1) { dst = g_Kh; ldd = D_ATT; col0 = 0; }
        else             { dst = g_Vh; ldd = D_VAL; col0 = (c - 2) * 64; }

        const int r0 = row0 + wid * 16 + g;
        #pragma unroll
        for (int nt = 0; nt < 8; nt++) {
            const int cc = col0 + nt * 8 + t4 * 2;
            *(uint32_t*)(dst + (size_t)r0 * ldd + cc) =
                pack_f16x2(C[nt][0] * sc, C[nt][1] * sc);
            *(uint32_t*)(dst + (size_t)(r0 + 8) * ldd + cc) =
                pack_f16x2(C[nt][2] * sc, C[nt][3] * sc);
        }

        if (c < 3) {
            CP_WAIT(0);
            __syncthreads();
        }
    }
}

// ---------------------------------------------------------------------------
// Kernel 2: 512-thread flash attention with split-K/split-V warp pairs.
// 16 warps: (qgroup 0..7, role 0..1). Role r computes S for keys [32r,32r+32),
// exps and publishes its P half via stmatrix, reads the partner half via
// ldmatrix after a barrier, then does PV for v-cols [64r,64r+64). No MMA is
// duplicated; O shrinks to 32 regs/warp -> 16 warps/SM.
// ---------------------------------------------------------------------------
#define SQH   0
#define SKBUF (SQH + 128 * 144)            // 18432
#define K_BUF_SZ (64 * 144)                // 9216
#define SVBUF (SKBUF + 2 * K_BUF_SZ)       // 36864
#define V_BUF_SZ (64 * 272)                // 17408
#define SPBUF (SVBUF + 2 * V_BUF_SZ)       // 71680 ; P: 128 x 64 fp16, stride 144
#define SMEM_TOTAL (SPBUF + 128 * 144)     // 90112

__global__ void __launch_bounds__(512, 1) fa_mma_kernel(float* __restrict__ out)
{
    extern __shared__ char smc[];
    const uint32_t sb = s2u(smc);
    const int tid  = threadIdx.x;
    const int wid  = tid >> 5;
    const int lane = tid & 31;
    const int b    = blockIdx.x >> 5;
    const int qt   = blockIdx.x & 31;
    const int qrow0 = b * S_DIM + qt * 128;
    const int qg   = wid & 7;              // query group (16 rows)
    const int role = wid >> 3;             // 0: k/v-lo half, 1: k/v-hi half
    const int g  = lane >> 2;
    const int t4 = lane & 3;

    // staging coords (512 threads)
    const int krow_st = tid >> 3, kcol_st = tid & 7;    // K: 1 iter
    const int vrow_st0 = tid >> 4, vcol_st = tid & 15;  // V: 2 iters of 512

    // ---- stage Q (128 rows x 8 units = 1024; 2/thread) ----
    #pragma unroll
    for (int i = 0; i < 2; i++) {
        int u = tid + i * 512;
        int row = u >> 3, c = u & 7;
        const size_t gs = (size_t)(qrow0 + row) * D_ATT + c * 8;
        CP_ASYNC16(sb + SQH + row * 144 + c * 16, (const char*)(g_Qh + gs));
    }
    CP_COMMIT();

    // ---- prefetch tile 0 into buffer 0 ----
    const int kbase0 = b * S_DIM;
    {
        const size_t gsk = (size_t)(kbase0 + krow_st) * D_ATT + kcol_st * 8;
        CP_ASYNC16(sb + SKBUF + krow_st * 144 + kcol_st * 16,
                   (const char*)(g_Kh + gsk));
        #pragma unroll
        for (int i = 0; i < 2; i++) {
            int u = tid + i * 512;
            int row = u >> 4;
            const size_t gs = (size_t)(kbase0 + row) * D_VAL + vcol_st * 8;
            CP_ASYNC16(sb + SVBUF + row * 272 + vcol_st * 16,
                       (const char*)(g_Vh + gs));
        }
    }
    CP_COMMIT();

    CP_WAIT(1);
    __syncthreads();

    // ---- Q fragments (persistent) ----
    const int rowq = qg * 16 + (lane & 15);
    const int colh = (lane >> 4) * 8;
    uint32_t qh[4][4];
    #pragma unroll
    for (int kk = 0; kk < 4; kk++)
        ldsm_x4(qh[kk], sb + SQH + rowq * 144 + (kk * 16 + colh) * 2);

    float O[8][4];
    #pragma unroll
    for (int i = 0; i < 8; i++)
        #pragma unroll
        for (int j = 0; j < 4; j++) O[i][j] = 0.f;
    float lacc[4] = {0.f, 0.f, 0.f, 0.f};

    const int krow = lane & 7;
    const int kq   = (lane >> 3) & 3;
    const uint32_t ONE2 = 0x3C003C00u;     // (fp16 1.0, fp16 1.0)
    const uint32_t prow_addr = sb + SPBUF + rowq * 144 + colh * 2;
    const int vcol_base = role * 128;      // byte offset of this warp's v-half

    #pragma unroll 1
    for (int kt = 0; kt < 64; kt++) {
        const int buf = kt & 1;

        CP_WAIT(0);
        __syncthreads();   // tile kt resident; prior tile's P reads all done

        const uint32_t kh = sb + SKBUF + buf * K_BUF_SZ;
        const uint32_t vh = sb + SVBUF + buf * V_BUF_SZ;

        // ---- S for own key half: keys [32*role, 32*role+32) ----
        float Sc[4][4];
        #pragma unroll
        for (int i = 0; i < 4; i++)
            #pragma unroll
            for (int j = 0; j < 4; j++) Sc[i][j] = 0.f;

        #pragma unroll
        for (int nt2 = 0; nt2 < 4; nt2++) {
            const int ntg = role * 4 + nt2;
            #pragma unroll
            for (int kp = 0; kp < 2; kp++) {
                uint32_t a = kh + (ntg * 8 + krow) * 144 + (kp * 32 + kq * 8) * 2;
                uint32_t bh[4];
                ldsm_x4(bh, a);
                mma_f16(Sc[nt2], qh[2 * kp],     bh[0], bh[1]);
                mma_f16(Sc[nt2], qh[2 * kp + 1], bh[2], bh[3]);
            }
        }

        // ---- mid-tile prefetch of tile kt+1 ----
        if (kt < 63) {
            const int kb = kbase0 + (kt + 1) * 64;
            const uint32_t dk = sb + SKBUF + (buf ^ 1) * K_BUF_SZ;
            const uint32_t dv = sb + SVBUF + (buf ^ 1) * V_BUF_SZ;
            const size_t gsk = (size_t)(kb + krow_st) * D_ATT + kcol_st * 8;
            CP_ASYNC16(dk + krow_st * 144 + kcol_st * 16,
                       (const char*)(g_Kh + gsk));
            #pragma unroll
            for (int i = 0; i < 2; i++) {
                int u = tid + i * 512;
                int row = u >> 4;
                const size_t gs = (size_t)(kb + row) * D_VAL + vcol_st * 8;
                CP_ASYNC16(dv + row * 272 + vcol_st * 16,
                           (const char*)(g_Vh + gs));
            }
            CP_COMMIT();
        }

        // ---- exp own half -> Ph chunks [2*role, 2*role+1] ----
        uint32_t Ph[4][4];
        #pragma unroll
        for (int nt2 = 0; nt2 < 4; nt2++) {
            uint32_t s01 = pack_f16x2(Sc[nt2][0], Sc[nt2][1]);
            uint32_t s23 = pack_f16x2(Sc[nt2][2], Sc[nt2][3]);
            const int kkg = role * 2 + (nt2 >> 1), half = nt2 & 1;
            Ph[kkg][half * 2 + 0] = ex2_f16x2(s01);
            Ph[kkg][half * 2 + 1] = ex2_f16x2(s23);
        }

        // ---- publish own P half ----
        #pragma unroll
        for (int kkl = 0; kkl < 2; kkl++) {
            const int kkg = role * 2 + kkl;
            stsm_x4(prow_addr + kkg * 32, Ph[kkg]);
        }
        __syncthreads();   // P exchange

        // ---- read partner's P half ----
        #pragma unroll
        for (int kkl = 0; kkl < 2; kkl++) {
            const int kko = (1 - role) * 2 + kkl;
            ldsm_x4(Ph[kko], prow_addr + kko * 32);
        }

        // ---- l += P @ ones (full row sum) ----
        #pragma unroll
        for (int kk = 0; kk < 4; kk++)
            mma_f16(lacc, Ph[kk], ONE2, ONE2);

        // ---- O += P V for own v-half: 8 n-tiles of 8 v-cols ----
        #pragma unroll
        for (int nt = 0; nt < 8; nt++) {
            #pragma unroll
            for (int kp = 0; kp < 2; kp++) {
                uint32_t a = vh + (kp * 32 + kq * 8 + krow) * 272
                           + vcol_base + nt * 16;
                uint32_t bh[4];
                ldsm_x4_t(bh, a);
                mma_f16(O[nt], Ph[2 * kp],     bh[0], bh[1]);
                mma_f16(O[nt], Ph[2 * kp + 1], bh[2], bh[3]);
            }
        }
    }

    // ---- epilogue: lacc holds complete row sums ----
    const float inv0 = 1.0f / lacc[0];
    const float inv1 = 1.0f / lacc[2];

    const int qa = qrow0 + qg * 16 + g;
    const int cb = role * 64;
    #pragma unroll
    for (int nt = 0; nt < 8; nt++) {
        *(float2*)(out + (size_t)qa * D_VAL + cb + nt * 8 + 2 * t4) =
            make_float2(O[nt][0] * inv0, O[nt][1] * inv0);
        *(float2*)(out + (size_t)(qa + 8) * D_VAL + cb + nt * 8 + 2 * t4) =
            make_float2(O[nt][2] * inv1, O[nt][3] * inv1);
    }
}

// ---------------------------------------------------------------------------
// Launch: wconv -> tensor-core proj -> split-pair flash attention.
// ---------------------------------------------------------------------------
extern "C" void kernel_launch(void* const* d_in, const int* in_sizes, int n_in,
                              void* d_out, int out_size)
{
    const float* x  = (const float*)d_in[0];
    const float* Wq = (const float*)d_in[1];
    const float* Wk = (const float*)d_in[2];
    const float* Wv = (const float*)d_in[3];
    float* out = (float*)d_out;

    (void)in_sizes; (void)n_in; (void)out_size;

    cudaFuncSetAttribute(proj_mma_kernel,
                         cudaFuncAttributeMaxDynamicSharedMemorySize,
                         PROJ_SMEM);
    cudaFuncSetAttribute(fa_mma_kernel,
                         cudaFuncAttributeMaxDynamicSharedMemorySize,
                         SMEM_TOTAL);

    wconv_kernel<<<(W_ROWS * D_VAL + 255) / 256, 256>>>(Wq, Wk, Wv);
    proj_mma_kernel<<<ROWS_TOTAL / 128, 256, PROJ_SMEM>>>(x);
    fa_mma_kernel<<<B_DIM * (S_DIM / 128), 512, SMEM_TOTAL>>>(out);
}

// round 10
// speedup vs baseline: 1.3206x; 1.3206x over previous
#include <cuda_runtime.h>
#include <cuda_fp16.h>
#include <stdint.h>

// ---------------------------------------------------------------------------
// Problem constants: B=4, S=4096, D=128, DA=64
// ---------------------------------------------------------------------------
#define B_DIM 4
#define S_DIM 4096
#define D_VAL 128
#define D_ATT 64
#define ROWS_TOTAL (B_DIM * S_DIM)   // 16384
#define W_ROWS 256                   // Wq(64) + Wk(64) + Wv(128)

// fp16 scratch (device globals: allocation-free per harness rules)
__device__ __align__(128) __half g_Qh[ROWS_TOTAL * D_ATT];
__device__ __align__(128) __half g_Kh[ROWS_TOTAL * D_ATT];
__device__ __align__(128) __half g_Vh[(size_t)ROWS_TOTAL * D_VAL];
__device__ __align__(128) __half g_Wh[W_ROWS * D_VAL];
__device__ __align__(128) __half g_Wl[W_ROWS * D_VAL];

// ---------------------------------------------------------------------------
// Small PTX helpers
// ---------------------------------------------------------------------------
#define CP_ASYNC16(dst, src) \
    asm volatile("cp.async.cg.shared.global [%0], [%1], 16;" \
                 :: "r"(dst), "l"(src) : "memory")
#define CP_COMMIT() asm volatile("cp.async.commit_group;" ::: "memory")
#define CP_WAIT(n)  asm volatile("cp.async.wait_group %0;" :: "n"(n) : "memory")

__device__ __forceinline__ uint32_t pack_f16x2(float f0, float f1) {
    // low 16 bits = f16(f0), high 16 bits = f16(f1)
    uint32_t r;
    asm("cvt.rn.f16x2.f32 %0, %1, %2;" : "=r"(r) : "f"(f1), "f"(f0));
    return r;
}

__device__ __forceinline__ uint32_t ex2_f16x2(uint32_t s) {
    uint32_t r;
    asm("ex2.approx.f16x2 %0, %1;" : "=r"(r) : "r"(s));
    return r;
}

__device__ __forceinline__ float h2f_lo(uint32_t u) {
    float f;
    asm("{ .reg .b16 h; mov.b16 h, %1; cvt.f32.f16 %0, h; }"
        : "=f"(f) : "h"((unsigned short)(u & 0xffffu)));
    return f;
}
__device__ __forceinline__ float h2f_hi(uint32_t u) {
    float f;
    asm("{ .reg .b16 h; mov.b16 h, %1; cvt.f32.f16 %0, h; }"
        : "=f"(f) : "h"((unsigned short)(u >> 16)));
    return f;
}

__device__ __forceinline__ uint32_t s2u(const void* p) {
    uint32_t a;
    asm("{ .reg .u64 t; cvta.to.shared.u64 t, %1; cvt.u32.u64 %0, t; }"
        : "=r"(a) : "l"(p));
    return a;
}

__device__ __forceinline__ void ldsm_x4(uint32_t (&r)[4], uint32_t addr) {
    asm volatile("ldmatrix.sync.aligned.m8n8.x4.shared.b16 {%0,%1,%2,%3}, [%4];"
                 : "=r"(r[0]), "=r"(r[1]), "=r"(r[2]), "=r"(r[3]) : "r"(addr));
}
__device__ __forceinline__ void ldsm_x4_t(uint32_t (&r)[4], uint32_t addr) {
    asm volatile("ldmatrix.sync.aligned.m8n8.x4.trans.shared.b16 {%0,%1,%2,%3}, [%4];"
                 : "=r"(r[0]), "=r"(r[1]), "=r"(r[2]), "=r"(r[3]) : "r"(addr));
}

__device__ __forceinline__ void mma_f16(float (&c)[4], const uint32_t (&a)[4],
                                        uint32_t b0, uint32_t b1) {
    asm volatile(
        "mma.sync.aligned.m16n8k16.row.col.f32.f16.f16.f32 "
        "{%0,%1,%2,%3},{%4,%5,%6,%7},{%8,%9},{%0,%1,%2,%3};"
        : "+f"(c[0]), "+f"(c[1]), "+f"(c[2]), "+f"(c[3])
        : "r"(a[0]), "r"(a[1]), "r"(a[2]), "r"(a[3]), "r"(b0), "r"(b1));
}

// ---------------------------------------------------------------------------
// Kernel 0: split weights into fp16 hi/lo, concatenated [Q(64) K(64) V(128)].
// ---------------------------------------------------------------------------
__global__ void __launch_bounds__(256) wconv_kernel(
    const float* __restrict__ Wq,
    const float* __restrict__ Wk,
    const float* __restrict__ Wv)
{
    const int gid = blockIdx.x * 256 + threadIdx.x;
    if (gid >= W_ROWS * D_VAL) return;
    const int row = gid >> 7;
    const int col = gid & 127;
    float v = (row < 64)  ? Wq[row * D_VAL + col]
            : (row < 128) ? Wk[(row - 64) * D_VAL + col]
                          : Wv[(row - 128) * D_VAL + col];
    uint32_t h = pack_f16x2(v, 0.f);
    g_Wh[gid] = __ushort_as_half((unsigned short)(h & 0xffffu));
    g_Wl[gid] = __float2half_rn(v - h2f_lo(h));
}

// ---------------------------------------------------------------------------
// Kernel 1: QKV projection on tensor cores (fp16 x3-pass: AhBh + AlBh + AhBl).
// Grid: 128 CTAs x 128 x-rows. 256 threads = 8 warps. (unchanged, ~11 us)
// ---------------------------------------------------------------------------
#define PX_H 0
#define PX_L (128 * 272)                   // 34816
#define PWBUF (2 * 128 * 272)              // 69632 ; per buf: h@0, l@+17408
#define PW_BUF_SZ (2 * 64 * 272)           // 34816
#define PROJ_SMEM (PWBUF + 2 * PW_BUF_SZ)  // 139264

__global__ void __launch_bounds__(256, 1) proj_mma_kernel(
    const float* __restrict__ x)
{
    extern __shared__ char smc[];
    const uint32_t sb = s2u(smc);
    const int tid  = threadIdx.x;
    const int wid  = tid >> 5;
    const int lane = tid & 31;
    const int row0 = blockIdx.x * 128;
    const int g  = lane >> 2;
    const int t4 = lane & 3;

    #pragma unroll
    for (int i = 0; i < 4; i++) {
        int u = tid + i * 256;
        int rr = u >> 4, cc = u & 15;
        uint32_t d = sb + PWBUF + rr * 272 + cc * 16;
        CP_ASYNC16(d,         (const char*)g_Wh + (size_t)rr * 256 + cc * 16);
        CP_ASYNC16(d + 17408, (const char*)g_Wl + (size_t)rr * 256 + cc * 16);
    }
    CP_COMMIT();

    #pragma unroll
    for (int i = 0; i < 16; i++) {
        int f4 = tid + i * 256;                    // 4096 float4 = 128x128
        int row = f4 >> 5, c4 = f4 & 31;
        float4 v = *(const float4*)(x + (size_t)(row0 + row) * D_VAL + c4 * 4);
        uint32_t h01 = pack_f16x2(v.x, v.y);
        uint32_t h23 = pack_f16x2(v.z, v.w);
        uint32_t l01 = pack_f16x2(v.x - h2f_lo(h01), v.y - h2f_hi(h01));
        uint32_t l23 = pack_f16x2(v.z - h2f_lo(h23), v.w - h2f_hi(h23));
        int off = row * 272 + c4 * 8;
        *(uint2*)(smc + off + PX_H) = make_uint2(h01, h23);
        *(uint2*)(smc + off + PX_L) = make_uint2(l01, l23);
    }
    CP_WAIT(0);
    __syncthreads();

    uint32_t ah[8][4], al[8][4];
    {
        const int rowq = wid * 16 + (lane & 15);
        const int colh = (lane >> 4) * 8;
        #pragma unroll
        for (int ks = 0; ks < 8; ks++) {
            uint32_t a = sb + PX_H + rowq * 272 + (ks * 16 + colh) * 2;
            ldsm_x4(ah[ks], a);
            ldsm_x4(al[ks], a + PX_L);
        }
    }

    const int krow = lane & 7;
    const int kq   = (lane >> 3) & 3;

    #pragma unroll 1
    for (int c = 0; c < 4; c++) {
        const int buf = c & 1;

        if (c < 3) {
            #pragma unroll
            for (int i = 0; i < 4; i++) {
                int u = tid + i * 256;
                int rr = u >> 4, cc = u & 15;
                uint32_t d = sb + PWBUF + (buf ^ 1) * PW_BUF_SZ + rr * 272 + cc * 16;
                const size_t gs = (size_t)((c + 1) * 64 + rr) * 256 + cc * 16;
                CP_ASYNC16(d,         (const char*)g_Wh + gs);
                CP_ASYNC16(d + 17408, (const char*)g_Wl + gs);
            }
            CP_COMMIT();
        }

        const uint32_t wb = sb + PWBUF + buf * PW_BUF_SZ;

        float C[8][4];
        #pragma unroll
        for (int i = 0; i < 8; i++)
            #pragma unroll
            for (int j = 0; j < 4; j++) C[i][j] = 0.f;

        #pragma unroll
        for (int kp = 0; kp < 4; kp++) {
            #pragma unroll
            for (int nt = 0; nt < 8; nt++) {
                uint32_t a = wb + (nt * 8 + krow) * 272 + (kp * 32 + kq * 8) * 2;
                uint32_t bh[4], bl[4];
                ldsm_x4(bh, a);
                ldsm_x4(bl, a + 17408);
                mma_f16(C[nt], ah[2 * kp],     bh[0], bh[1]);
                mma_f16(C[nt], al[2 * kp],     bh[0], bh[1]);
                mma_f16(C[nt], ah[2 * kp],     bl[0], bl[1]);
                mma_f16(C[nt], ah[2 * kp + 1], bh[2], bh[3]);
                mma_f16(C[nt], al[2 * kp + 1], bh[2], bh[3]);
                mma_f16(C[nt], ah[2 * kp + 1], bl[2], bl[3]);
            }
        }

        const float sc = (c == 0) ? 0.18033688f : 1.0f;  // 0.125 * log2(e)
        __half* dst;
        int ldd, col0;
        if (c == 0)      { dst = g_Qh; ldd = D_ATT; col0 = 0; }
        else if (c == 1) { dst = g_Kh; ldd = D_ATT; col0 = 0; }
        else             { dst = g_Vh; ldd = D_VAL; col0 = (c - 2) * 64; }

        const int r0 = row0 + wid * 16 + g;
        #pragma unroll
        for (int nt = 0; nt < 8; nt++) {
            const int cc = col0 + nt * 8 + t4 * 2;
            *(uint32_t*)(dst + (size_t)r0 * ldd + cc) =
                pack_f16x2(C[nt][0] * sc, C[nt][1] * sc);
            *(uint32_t*)(dst + (size_t)(r0 + 8) * ldd + cc) =
                pack_f16x2(C[nt][2] * sc, C[nt][3] * sc);
        }

        if (c < 3) {
            CP_WAIT(0);
            __syncthreads();
        }
    }
}

// ---------------------------------------------------------------------------
// Kernel 2: 512-thread flash attention, S-duplicated v-split (NO extra sync).
// 16 warps = (qgroup 0..7) x (vhalf 0..1). Both warps of a pair compute the
// full S row block and exp (fused per-nt into the S loop: MMA->pack->ex2),
// then each does PV only for its own 64 v-columns. One barrier per tile,
// exactly as the 100us R8 kernel.
// ---------------------------------------------------------------------------
#define SQH   0
#define SKBUF (SQH + 128 * 144)            // 18432
#define K_BUF_SZ (64 * 144)                // 9216
#define SVBUF (SKBUF + 2 * K_BUF_SZ)       // 36864
#define V_BUF_SZ (64 * 272)                // 17408
#define SMEM_TOTAL (SVBUF + 2 * V_BUF_SZ)  // 71680

__global__ void __launch_bounds__(512, 1) fa_mma_kernel(float* __restrict__ out)
{
    extern __shared__ char smc[];
    const uint32_t sb = s2u(smc);
    const int tid  = threadIdx.x;
    const int wid  = tid >> 5;
    const int lane = tid & 31;
    const int b    = blockIdx.x >> 5;
    const int qt   = blockIdx.x & 31;
    const int qrow0 = b * S_DIM + qt * 128;
    const int qg    = wid & 7;             // query group (16 rows)
    const int vhalf = wid >> 3;            // which 64 v-columns this warp owns
    const int g  = lane >> 2;
    const int t4 = lane & 3;

    // staging coords (512 threads)
    const int krow_st = tid >> 3, kcol_st = tid & 7;   // K: 64x8 units, 1 iter
    const int vcol_st = tid & 15;                      // V: 2 iters of 512

    // ---- stage Q (128 rows x 8 units = 1024; 2/thread) ----
    #pragma unroll
    for (int i = 0; i < 2; i++) {
        int u = tid + i * 512;
        int row = u >> 3, c = u & 7;
        const size_t gs = (size_t)(qrow0 + row) * D_ATT + c * 8;
        CP_ASYNC16(sb + SQH + row * 144 + c * 16, (const char*)(g_Qh + gs));
    }
    CP_COMMIT();

    // ---- prefetch tile 0 into buffer 0 ----
    const int kbase0 = b * S_DIM;
    {
        const size_t gsk = (size_t)(kbase0 + krow_st) * D_ATT + kcol_st * 8;
        CP_ASYNC16(sb + SKBUF + krow_st * 144 + kcol_st * 16,
                   (const char*)(g_Kh + gsk));
        #pragma unroll
        for (int i = 0; i < 2; i++) {
            int u = tid + i * 512;
            int row = u >> 4;
            const size_t gs = (size_t)(kbase0 + row) * D_VAL + vcol_st * 8;
            CP_ASYNC16(sb + SVBUF + row * 272 + vcol_st * 16,
                       (const char*)(g_Vh + gs));
        }
    }
    CP_COMMIT();

    CP_WAIT(1);
    __syncthreads();

    // ---- Q fragments (persistent) ----
    const int rowq = qg * 16 + (lane & 15);
    const int colh = (lane >> 4) * 8;
    uint32_t qh[4][4];
    #pragma unroll
    for (int kk = 0; kk < 4; kk++)
        ldsm_x4(qh[kk], sb + SQH + rowq * 144 + (kk * 16 + colh) * 2);

    float O[8][4];
    #pragma unroll
    for (int i = 0; i < 8; i++)
        #pragma unroll
        for (int j = 0; j < 4; j++) O[i][j] = 0.f;
    float lacc[4] = {0.f, 0.f, 0.f, 0.f};

    const int krow = lane & 7;
    const int kq   = (lane >> 3) & 3;
    const uint32_t ONE2 = 0x3C003C00u;     // (fp16 1.0, fp16 1.0)
    const int vcol_base = vhalf * 128;     // byte offset of this warp's v-half

    #pragma unroll 1
    for (int kt = 0; kt < 64; kt++) {
        const int buf = kt & 1;

        CP_WAIT(0);
        __syncthreads();   // tile kt resident; all warps past tile kt-1

        const uint32_t kh = sb + SKBUF + buf * K_BUF_SZ;
        const uint32_t vh = sb + SVBUF + buf * V_BUF_SZ;

        // ---- S + exp, fused per 8-key tile: 4 MMA -> pack -> ex2 ----
        // (Sc liveness is 4 regs; MUFU latency hides under next nt's MMAs.)
        uint32_t Ph[4][4];
        #pragma unroll
        for (int nt = 0; nt < 8; nt++) {
            float Sc[4] = {0.f, 0.f, 0.f, 0.f};
            #pragma unroll
            for (int kp = 0; kp < 2; kp++) {
                uint32_t a = kh + (nt * 8 + krow) * 144 + (kp * 32 + kq * 8) * 2;
                uint32_t bh[4];
                ldsm_x4(bh, a);
                mma_f16(Sc, qh[2 * kp],     bh[0], bh[1]);
                mma_f16(Sc, qh[2 * kp + 1], bh[2], bh[3]);
            }
            uint32_t s01 = pack_f16x2(Sc[0], Sc[1]);
            uint32_t s23 = pack_f16x2(Sc[2], Sc[3]);
            Ph[nt >> 1][(nt & 1) * 2 + 0] = ex2_f16x2(s01);
            Ph[nt >> 1][(nt & 1) * 2 + 1] = ex2_f16x2(s23);
        }

        // ---- mid-tile prefetch of tile kt+1 into buf^1 ----
        if (kt < 63) {
            const int kb = kbase0 + (kt + 1) * 64;
            const uint32_t dk = sb + SKBUF + (buf ^ 1) * K_BUF_SZ;
            const uint32_t dv = sb + SVBUF + (buf ^ 1) * V_BUF_SZ;
            const size_t gsk = (size_t)(kb + krow_st) * D_ATT + kcol_st * 8;
            CP_ASYNC16(dk + krow_st * 144 + kcol_st * 16,
                       (const char*)(g_Kh + gsk));
            #pragma unroll
            for (int i = 0; i < 2; i++) {
                int u = tid + i * 512;
                int row = u >> 4;
                const size_t gs = (size_t)(kb + row) * D_VAL + vcol_st * 8;
                CP_ASYNC16(dv + row * 272 + vcol_st * 16,
                           (const char*)(g_Vh + gs));
            }
            CP_COMMIT();
        }

        // ---- l += P @ ones (tensor-core full row sum) ----
        #pragma unroll
        for (int kk = 0; kk < 4; kk++)
            mma_f16(lacc, Ph[kk], ONE2, ONE2);

        // ---- O += P V for own v-half: 8 n-tiles of 8 v-cols ----
        #pragma unroll
        for (int nt = 0; nt < 8; nt++) {
            #pragma unroll
            for (int kp = 0; kp < 2; kp++) {
                uint32_t a = vh + (kp * 32 + kq * 8 + krow) * 272
                           + vcol_base + nt * 16;
                uint32_t bh[4];
                ldsm_x4_t(bh, a);
                mma_f16(O[nt], Ph[2 * kp],     bh[0], bh[1]);
                mma_f16(O[nt], Ph[2 * kp + 1], bh[2], bh[3]);
            }
        }
    }

    // ---- epilogue: lacc holds complete row sums ----
    const float inv0 = 1.0f / lacc[0];
    const float inv1 = 1.0f / lacc[2];

    const int qa = qrow0 + qg * 16 + g;
    const int cb = vhalf * 64;
    #pragma unroll
    for (int nt = 0; nt < 8; nt++) {
        *(float2*)(out + (size_t)qa * D_VAL + cb + nt * 8 + 2 * t4) =
            make_float2(O[nt][0] * inv0, O[nt][1] * inv0);
        *(float2*)(out + (size_t)(qa + 8) * D_VAL + cb + nt * 8 + 2 * t4) =
            make_float2(O[nt][2] * inv1, O[nt][3] * inv1);
    }
}

// ---------------------------------------------------------------------------
// Launch: wconv -> tensor-core proj -> S-duplicated v-split flash attention.
// ---------------------------------------------------------------------------
extern "C" void kernel_launch(void* const* d_in, const int* in_sizes, int n_in,
                              void* d_out, int out_size)
{
    const float* x  = (const float*)d_in[0];
    const float* Wq = (const float*)d_in[1];
    const float* Wk = (const float*)d_in[2];
    const float* Wv = (const float*)d_in[3];
    float* out = (float*)d_out;

    (void)in_sizes; (void)n_in; (void)out_size;

    cudaFuncSetAttribute(proj_mma_kernel,
                         cudaFuncAttributeMaxDynamicSharedMemorySize,
                         PROJ_SMEM);
    cudaFuncSetAttribute(fa_mma_kernel,
                         cudaFuncAttributeMaxDynamicSharedMemorySize,
                         SMEM_TOTAL);

    wconv_kernel<<<(W_ROWS * D_VAL + 255) / 256, 256>>>(Wq, Wk, Wv);
    proj_mma_kernel<<<ROWS_TOTAL / 128, 256, PROJ_SMEM>>>(x);
    fa_mma_kernel<<<B_DIM * (S_DIM / 128), 512, SMEM_TOTAL>>>(out);
}

// round 11
// speedup vs baseline: 1.4190x; 1.0745x over previous
#include <cuda_runtime.h>
#include <cuda_fp16.h>
#include <stdint.h>

// ---------------------------------------------------------------------------
// Problem constants: B=4, S=4096, D=128, DA=64
// ---------------------------------------------------------------------------
#define B_DIM 4
#define S_DIM 4096
#define D_VAL 128
#define D_ATT 64
#define ROWS_TOTAL (B_DIM * S_DIM)   // 16384
#define W_ROWS 256                   // Wq(64) + Wk(64) + Wv(128)

// fp16 scratch (device globals: allocation-free per harness rules)
__device__ __align__(128) __half g_Qh[ROWS_TOTAL * D_ATT];
__device__ __align__(128) __half g_Kh[ROWS_TOTAL * D_ATT];
__device__ __align__(128) __half g_Vh[(size_t)ROWS_TOTAL * D_VAL];
__device__ __align__(128) __half g_Wh[W_ROWS * D_VAL];
__device__ __align__(128) __half g_Wl[W_ROWS * D_VAL];

// ---------------------------------------------------------------------------
// Small PTX helpers
// ---------------------------------------------------------------------------
#define CP_ASYNC16(dst, src) \
    asm volatile("cp.async.cg.shared.global [%0], [%1], 16;" \
                 :: "r"(dst), "l"(src) : "memory")
#define CP_COMMIT() asm volatile("cp.async.commit_group;" ::: "memory")
#define CP_WAIT(n)  asm volatile("cp.async.wait_group %0;" :: "n"(n) : "memory")

__device__ __forceinline__ uint32_t pack_f16x2(float f0, float f1) {
    // low 16 bits = f16(f0), high 16 bits = f16(f1)
    uint32_t r;
    asm("cvt.rn.f16x2.f32 %0, %1, %2;" : "=r"(r) : "f"(f1), "f"(f0));
    return r;
}

__device__ __forceinline__ uint32_t ex2_f16x2(uint32_t s) {
    uint32_t r;
    asm("ex2.approx.f16x2 %0, %1;" : "=r"(r) : "r"(s));
    return r;
}

__device__ __forceinline__ float h2f_lo(uint32_t u) {
    float f;
    asm("{ .reg .b16 h; mov.b16 h, %1; cvt.f32.f16 %0, h; }"
        : "=f"(f) : "h"((unsigned short)(u & 0xffffu)));
    return f;
}
__device__ __forceinline__ float h2f_hi(uint32_t u) {
    float f;
    asm("{ .reg .b16 h; mov.b16 h, %1; cvt.f32.f16 %0, h; }"
        : "=f"(f) : "h"((unsigned short)(u >> 16)));
    return f;
}

__device__ __forceinline__ uint32_t s2u(const void* p) {
    uint32_t a;
    asm("{ .reg .u64 t; cvta.to.shared.u64 t, %1; cvt.u32.u64 %0, t; }"
        : "=r"(a) : "l"(p));
    return a;
}

__device__ __forceinline__ void ldsm_x4(uint32_t (&r)[4], uint32_t addr) {
    asm volatile("ldmatrix.sync.aligned.m8n8.x4.shared.b16 {%0,%1,%2,%3}, [%4];"
                 : "=r"(r[0]), "=r"(r[1]), "=r"(r[2]), "=r"(r[3]) : "r"(addr));
}
__device__ __forceinline__ void ldsm_x4_t(uint32_t (&r)[4], uint32_t addr) {
    asm volatile("ldmatrix.sync.aligned.m8n8.x4.trans.shared.b16 {%0,%1,%2,%3}, [%4];"
                 : "=r"(r[0]), "=r"(r[1]), "=r"(r[2]), "=r"(r[3]) : "r"(addr));
}

__device__ __forceinline__ void mma_f16(float (&c)[4], const uint32_t (&a)[4],
                                        uint32_t b0, uint32_t b1) {
    asm volatile(
        "mma.sync.aligned.m16n8k16.row.col.f32.f16.f16.f32 "
        "{%0,%1,%2,%3},{%4,%5,%6,%7},{%8,%9},{%0,%1,%2,%3};"
        : "+f"(c[0]), "+f"(c[1]), "+f"(c[2]), "+f"(c[3])
        : "r"(a[0]), "r"(a[1]), "r"(a[2]), "r"(a[3]), "r"(b0), "r"(b1));
}

// ---------------------------------------------------------------------------
// Kernel 0: split weights into fp16 hi/lo, concatenated [Q(64) K(64) V(128)].
// ---------------------------------------------------------------------------
__global__ void __launch_bounds__(256) wconv_kernel(
    const float* __restrict__ Wq,
    const float* __restrict__ Wk,
    const float* __restrict__ Wv)
{
    const int gid = blockIdx.x * 256 + threadIdx.x;
    if (gid >= W_ROWS * D_VAL) return;
    const int row = gid >> 7;
    const int col = gid & 127;
    float v = (row < 64)  ? Wq[row * D_VAL + col]
            : (row < 128) ? Wk[(row - 64) * D_VAL + col]
                          : Wv[(row - 128) * D_VAL + col];
    uint32_t h = pack_f16x2(v, 0.f);
    g_Wh[gid] = __ushort_as_half((unsigned short)(h & 0xffffu));
    g_Wl[gid] = __float2half_rn(v - h2f_lo(h));
}

// ---------------------------------------------------------------------------
// Kernel 1: QKV projection on tensor cores (fp16 x3-pass: AhBh + AlBh + AhBl).
// Grid: 128 CTAs x 128 x-rows. 256 threads = 8 warps. (unchanged, ~11 us)
// ---------------------------------------------------------------------------
#define PX_H 0
#define PX_L (128 * 272)                   // 34816
#define PWBUF (2 * 128 * 272)              // 69632 ; per buf: h@0, l@+17408
#define PW_BUF_SZ (2 * 64 * 272)           // 34816
#define PROJ_SMEM (PWBUF + 2 * PW_BUF_SZ)  // 139264

__global__ void __launch_bounds__(256, 1) proj_mma_kernel(
    const float* __restrict__ x)
{
    extern __shared__ char smc[];
    const uint32_t sb = s2u(smc);
    const int tid  = threadIdx.x;
    const int wid  = tid >> 5;
    const int lane = tid & 31;
    const int row0 = blockIdx.x * 128;
    const int g  = lane >> 2;
    const int t4 = lane & 3;

    #pragma unroll
    for (int i = 0; i < 4; i++) {
        int u = tid + i * 256;
        int rr = u >> 4, cc = u & 15;
        uint32_t d = sb + PWBUF + rr * 272 + cc * 16;
        CP_ASYNC16(d,         (const char*)g_Wh + (size_t)rr * 256 + cc * 16);
        CP_ASYNC16(d + 17408, (const char*)g_Wl + (size_t)rr * 256 + cc * 16);
    }
    CP_COMMIT();

    #pragma unroll
    for (int i = 0; i < 16; i++) {
        int f4 = tid + i * 256;                    // 4096 float4 = 128x128
        int row = f4 >> 5, c4 = f4 & 31;
        float4 v = *(const float4*)(x + (size_t)(row0 + row) * D_VAL + c4 * 4);
        uint32_t h01 = pack_f16x2(v.x, v.y);
        uint32_t h23 = pack_f16x2(v.z, v.w);
        uint32_t l01 = pack_f16x2(v.x - h2f_lo(h01), v.y - h2f_hi(h01));
        uint32_t l23 = pack_f16x2(v.z - h2f_lo(h23), v.w - h2f_hi(h23));
        int off = row * 272 + c4 * 8;
        *(uint2*)(smc + off + PX_H) = make_uint2(h01, h23);
        *(uint2*)(smc + off + PX_L) = make_uint2(l01, l23);
    }
    CP_WAIT(0);
    __syncthreads();

    uint32_t ah[8][4], al[8][4];
    {
        const int rowq = wid * 16 + (lane & 15);
        const int colh = (lane >> 4) * 8;
        #pragma unroll
        for (int ks = 0; ks < 8; ks++) {
            uint32_t a = sb + PX_H + rowq * 272 + (ks * 16 + colh) * 2;
            ldsm_x4(ah[ks], a);
            ldsm_x4(al[ks], a + PX_L);
        }
    }

    const int krow = lane & 7;
    const int kq   = (lane >> 3) & 3;

    #pragma unroll 1
    for (int c = 0; c < 4; c++) {
        const int buf = c & 1;

        if (c < 3) {
            #pragma unroll
            for (int i = 0; i < 4; i++) {
                int u = tid + i * 256;
                int rr = u >> 4, cc = u & 15;
                uint32_t d = sb + PWBUF + (buf ^ 1) * PW_BUF_SZ + rr * 272 + cc * 16;
                const size_t gs = (size_t)((c + 1) * 64 + rr) * 256 + cc * 16;
                CP_ASYNC16(d,         (const char*)g_Wh + gs);
                CP_ASYNC16(d + 17408, (const char*)g_Wl + gs);
            }
            CP_COMMIT();
        }

        const uint32_t wb = sb + PWBUF + buf * PW_BUF_SZ;

        float C[8][4];
        #pragma unroll
        for (int i = 0; i < 8; i++)
            #pragma unroll
            for (int j = 0; j < 4; j++) C[i][j] = 0.f;

        #pragma unroll
        for (int kp = 0; kp < 4; kp++) {
            #pragma unroll
            for (int nt = 0; nt < 8; nt++) {
                uint32_t a = wb + (nt * 8 + krow) * 272 + (kp * 32 + kq * 8) * 2;
                uint32_t bh[4], bl[4];
                ldsm_x4(bh, a);
                ldsm_x4(bl, a + 17408);
                mma_f16(C[nt], ah[2 * kp],     bh[0], bh[1]);
                mma_f16(C[nt], al[2 * kp],     bh[0], bh[1]);
                mma_f16(C[nt], ah[2 * kp],     bl[0], bl[1]);
                mma_f16(C[nt], ah[2 * kp + 1], bh[2], bh[3]);
                mma_f16(C[nt], al[2 * kp + 1], bh[2], bh[3]);
                mma_f16(C[nt], ah[2 * kp + 1], bl[2], bl[3]);
            }
        }

        const float sc = (c == 0) ? 0.18033688f : 1.0f;  // 0.125 * log2(e)
        __half* dst;
        int ldd, col0;
        if (c == 0)      { dst = g_Qh; ldd = D_ATT; col0 = 0; }
        else if (c == 1) { dst = g_Kh; ldd = D_ATT; col0 = 0; }
        else             { dst = g_Vh; ldd = D_VAL; col0 = (c - 2) * 64; }

        const int r0 = row0 + wid * 16 + g;
        #pragma unroll
        for (int nt = 0; nt < 8; nt++) {
            const int cc = col0 + nt * 8 + t4 * 2;
            *(uint32_t*)(dst + (size_t)r0 * ldd + cc) =
                pack_f16x2(C[nt][0] * sc, C[nt][1] * sc);
            *(uint32_t*)(dst + (size_t)(r0 + 8) * ldd + cc) =
                pack_f16x2(C[nt][2] * sc, C[nt][3] * sc);
        }

        if (c < 3) {
            CP_WAIT(0);
            __syncthreads();
        }
    }
}

// ---------------------------------------------------------------------------
// Kernel 2: flash attention, 128 threads / 4 warps per CTA, q-tile 64,
// 2 CTAs co-resident per SM (61 KB smem each). Per-warp work identical to
// the R8 kernel (q16 x k64 x v128, 1 barrier/tile): no duplicated MMAs, no
// added sync — the co-resident CTA provides the latency hiding. exp fused
// into the S loop (Sc liveness 4 regs; MUFU overlaps next nt's MMAs).
// ---------------------------------------------------------------------------
#define SQH   0
#define SKBUF (SQH + 64 * 144)             // 9216
#define K_BUF_SZ (64 * 144)                // 9216
#define SVBUF (SKBUF + 2 * K_BUF_SZ)       // 27648
#define V_BUF_SZ (64 * 272)                // 17408
#define SMEM_TOTAL (SVBUF + 2 * V_BUF_SZ)  // 62464

__global__ void __launch_bounds__(128, 2) fa_mma_kernel(float* __restrict__ out)
{
    extern __shared__ char smc[];
    const uint32_t sb = s2u(smc);
    const int tid  = threadIdx.x;
    const int wid  = tid >> 5;              // 0..3, q-group
    const int lane = tid & 31;
    const int b    = blockIdx.x >> 6;
    const int qt   = blockIdx.x & 63;
    const int qrow0 = b * S_DIM + qt * 64;
    const int g  = lane >> 2;
    const int t4 = lane & 3;

    // staging coords (128 threads)
    const int krow_st = tid >> 3, kcol_st = tid & 7;   // K: rows +16 per iter
    const int vrow_st = tid >> 4, vcol_st = tid & 15;  // V: rows +8 per iter

    // ---- stage Q (64 rows x 8 units = 512; 4/thread) ----
    #pragma unroll
    for (int i = 0; i < 4; i++) {
        int u = tid + i * 128;
        int row = u >> 3, c = u & 7;
        const size_t gs = (size_t)(qrow0 + row) * D_ATT + c * 8;
        CP_ASYNC16(sb + SQH + row * 144 + c * 16, (const char*)(g_Qh + gs));
    }
    CP_COMMIT();

    // ---- prefetch tile 0 into buffer 0 ----
    const int kbase0 = b * S_DIM;
    {
        #pragma unroll
        for (int i = 0; i < 4; i++) {
            int row = krow_st + i * 16;
            const size_t gs = (size_t)(kbase0 + row) * D_ATT + kcol_st * 8;
            CP_ASYNC16(sb + SKBUF + row * 144 + kcol_st * 16,
                       (const char*)(g_Kh + gs));
        }
        #pragma unroll
        for (int i = 0; i < 8; i++) {
            int row = vrow_st + i * 8;
            const size_t gs = (size_t)(kbase0 + row) * D_VAL + vcol_st * 8;
            CP_ASYNC16(sb + SVBUF + row * 272 + vcol_st * 16,
                       (const char*)(g_Vh + gs));
        }
    }
    CP_COMMIT();

    CP_WAIT(1);
    __syncthreads();

    // ---- Q fragments (persistent) ----
    const int rowq = wid * 16 + (lane & 15);
    const int colh = (lane >> 4) * 8;
    uint32_t qh[4][4];
    #pragma unroll
    for (int kk = 0; kk < 4; kk++)
        ldsm_x4(qh[kk], sb + SQH + rowq * 144 + (kk * 16 + colh) * 2);

    float O[16][4];
    #pragma unroll
    for (int i = 0; i < 16; i++)
        #pragma unroll
        for (int j = 0; j < 4; j++) O[i][j] = 0.f;
    float lacc[4] = {0.f, 0.f, 0.f, 0.f};

    const int krow = lane & 7;
    const int kq   = (lane >> 3) & 3;
    const uint32_t ONE2 = 0x3C003C00u;     // (fp16 1.0, fp16 1.0)

    #pragma unroll 1
    for (int kt = 0; kt < 64; kt++) {
        const int buf = kt & 1;

        CP_WAIT(0);
        __syncthreads();   // tile kt resident; all warps past tile kt-1

        const uint32_t kh = sb + SKBUF + buf * K_BUF_SZ;
        const uint32_t vh = sb + SVBUF + buf * V_BUF_SZ;

        // ---- S + exp, fused per 8-key tile: 4 MMA -> pack -> ex2 ----
        uint32_t Ph[4][4];
        #pragma unroll
        for (int nt = 0; nt < 8; nt++) {
            float Sc[4] = {0.f, 0.f, 0.f, 0.f};
            #pragma unroll
            for (int kp = 0; kp < 2; kp++) {
                uint32_t a = kh + (nt * 8 + krow) * 144 + (kp * 32 + kq * 8) * 2;
                uint32_t bh[4];
                ldsm_x4(bh, a);
                mma_f16(Sc, qh[2 * kp],     bh[0], bh[1]);
                mma_f16(Sc, qh[2 * kp + 1], bh[2], bh[3]);
            }
            uint32_t s01 = pack_f16x2(Sc[0], Sc[1]);
            uint32_t s23 = pack_f16x2(Sc[2], Sc[3]);
            Ph[nt >> 1][(nt & 1) * 2 + 0] = ex2_f16x2(s01);
            Ph[nt >> 1][(nt & 1) * 2 + 1] = ex2_f16x2(s23);
        }

        // ---- mid-tile prefetch of tile kt+1 into buf^1 ----
        if (kt < 63) {
            const int kb = kbase0 + (kt + 1) * 64;
            const uint32_t dk = sb + SKBUF + (buf ^ 1) * K_BUF_SZ;
            const uint32_t dv = sb + SVBUF + (buf ^ 1) * V_BUF_SZ;
            #pragma unroll
            for (int i = 0; i < 4; i++) {
                int row = krow_st + i * 16;
                const size_t gs = (size_t)(kb + row) * D_ATT + kcol_st * 8;
                CP_ASYNC16(dk + row * 144 + kcol_st * 16,
                           (const char*)(g_Kh + gs));
            }
            #pragma unroll
            for (int i = 0; i < 8; i++) {
                int row = vrow_st + i * 8;
                const size_t gs = (size_t)(kb + row) * D_VAL + vcol_st * 8;
                CP_ASYNC16(dv + row * 272 + vcol_st * 16,
                           (const char*)(g_Vh + gs));
            }
            CP_COMMIT();
        }

        // ---- l += P @ ones (tensor-core full row sum) ----
        #pragma unroll
        for (int kk = 0; kk < 4; kk++)
            mma_f16(lacc, Ph[kk], ONE2, ONE2);

        // ---- O += P V: 16 n-tiles of 8 v-cols ----
        #pragma unroll
        for (int nt = 0; nt < 16; nt++) {
            #pragma unroll
            for (int kp = 0; kp < 2; kp++) {
                uint32_t a = vh + (kp * 32 + kq * 8 + krow) * 272 + nt * 16;
                uint32_t bh[4];
                ldsm_x4_t(bh, a);
                mma_f16(O[nt], Ph[2 * kp],     bh[0], bh[1]);
                mma_f16(O[nt], Ph[2 * kp + 1], bh[2], bh[3]);
            }
        }
    }

    // ---- epilogue: lacc holds complete row sums ----
    const float inv0 = 1.0f / lacc[0];
    const float inv1 = 1.0f / lacc[2];

    const int qa = qrow0 + wid * 16 + g;
    #pragma unroll
    for (int nt = 0; nt < 16; nt++) {
        *(float2*)(out + (size_t)qa * D_VAL + nt * 8 + 2 * t4) =
            make_float2(O[nt][0] * inv0, O[nt][1] * inv0);
        *(float2*)(out + (size_t)(qa + 8) * D_VAL + nt * 8 + 2 * t4) =
            make_float2(O[nt][2] * inv1, O[nt][3] * inv1);
    }
}

// ---------------------------------------------------------------------------
// Launch: wconv -> tensor-core proj -> 2-CTA/SM flash attention.
// ---------------------------------------------------------------------------
extern "C" void kernel_launch(void* const* d_in, const int* in_sizes, int n_in,
                              void* d_out, int out_size)
{
    const float* x  = (const float*)d_in[0];
    const float* Wq = (const float*)d_in[1];
    const float* Wk = (const float*)d_in[2];
    const float* Wv = (const float*)d_in[3];
    float* out = (float*)d_out;

    (void)in_sizes; (void)n_in; (void)out_size;

    cudaFuncSetAttribute(proj_mma_kernel,
                         cudaFuncAttributeMaxDynamicSharedMemorySize,
                         PROJ_SMEM);
    cudaFuncSetAttribute(fa_mma_kernel,
                         cudaFuncAttributeMaxDynamicSharedMemorySize,
                         SMEM_TOTAL);

    wconv_kernel<<<(W_ROWS * D_VAL + 255) / 256, 256>>>(Wq, Wk, Wv);
    proj_mma_kernel<<<ROWS_TOTAL / 128, 256, PROJ_SMEM>>>(x);
    fa_mma_kernel<<<B_DIM * (S_DIM / 64), 128, SMEM_TOTAL>>>(out);
}